// round 16
// baseline (speedup 1.0000x reference)
#include <cuda_runtime.h>
#include <cuda_fp16.h>
#include <math.h>
#include <stdint.h>

// ---------------- problem constants ----------------
#define B_   2
#define S_   512
#define L_   12
#define H_   1024
#define NH_  16
#define DH_  64
#define FF_  4096
#define R2_  1024          // 2*SPAN
#define BS_  (B_*S_)       // 1024
#define BW_  640           // band width for c2p/p2c
#define ZBH_ (B_*NH_)      // 32
#define LN_EPS_ 1e-7f

// ---------------- fp32 scratch ----------------
__device__ float g_h   [BS_*H_];
__device__ float g_qkv [BS_*3*H_];
__device__ float g_band[(size_t)2*B_*NH_*S_*BW_];  // [c2p(32) | p2c(32)] banded
__device__ float g_t2  [BS_*H_];

// ---------------- fp16 split weight buffers ----------------
#define NIW  (L_*3*H_*H_)
#define NPW  (L_*H_*H_)
#define NW1  (L_*FF_*H_)
__device__ __half g_wih [NIW], g_wil [NIW];
__device__ __half g_ppwh[2*NPW], g_ppwl[2*NPW];   // [0][l]=pos_k_w, [1][l]=pos_q_w
__device__ __half g_aowh[NPW], g_aowl[NPW];
__device__ __half g_w1h [NW1], g_w1l [NW1];
__device__ __half g_w2h [NW1], g_w2l [NW1];
__device__ __half g_relh[R2_*H_], g_rell[R2_*H_];

// ---------------- fp16 split activation buffers ----------------
__device__ __half g_hh [BS_*H_], g_hl [BS_*H_];
__device__ __half g_qh [BS_*H_], g_ql [BS_*H_];
__device__ __half g_kh [BS_*H_], g_kl [BS_*H_];
__device__ __half g_vTh[BS_*H_], g_vTl[BS_*H_];
__device__ __half g_ppoh[(size_t)2*L_*R2_*H_], g_ppol[(size_t)2*L_*R2_*H_];  // [which][l][R2*H]
__device__ __half g_cxh[BS_*H_], g_cxl[BS_*H_];
__device__ __half g_ffh[BS_*FF_], g_ffl[BS_*FF_];

// ---------------- asm helpers ----------------
__device__ __forceinline__ uint32_t smem_u32(const void* p) {
    uint32_t a;
    asm("{ .reg .u64 t; cvta.to.shared.u64 t, %1; cvt.u32.u64 %0, t; }"
        : "=r"(a) : "l"(p));
    return a;
}
__device__ __forceinline__ void cp16(uint32_t dst, const void* src) {
    asm volatile("cp.async.cg.shared.global [%0], [%1], 16;" :: "r"(dst), "l"(src));
}
__device__ __forceinline__ void cp_commit() {
    asm volatile("cp.async.commit_group;" ::: "memory");
}
template<int N> __device__ __forceinline__ void cp_wait() {
    asm volatile("cp.async.wait_group %0;" :: "n"(N) : "memory");
}
__device__ __forceinline__ void ldsm4(uint32_t* d, uint32_t a) {
    asm volatile("ldmatrix.sync.aligned.m8n8.x4.shared.b16 {%0,%1,%2,%3}, [%4];"
        : "=r"(d[0]), "=r"(d[1]), "=r"(d[2]), "=r"(d[3]) : "r"(a));
}
__device__ __forceinline__ void mma16816(float* c, const uint32_t* a, const uint32_t* b) {
    asm volatile(
        "mma.sync.aligned.m16n8k16.row.col.f32.f16.f16.f32 "
        "{%0,%1,%2,%3}, {%4,%5,%6,%7}, {%8,%9}, {%0,%1,%2,%3};"
        : "+f"(c[0]), "+f"(c[1]), "+f"(c[2]), "+f"(c[3])
        : "r"(a[0]), "r"(a[1]), "r"(a[2]), "r"(a[3]), "r"(b[0]), "r"(b[1]));
}
__device__ __forceinline__ float gelu_f(float x) {
    float t = tanhf(0.7978845608028654f * (x + 0.044715f * x * x * x));
    return 0.5f * x * (1.0f + t);
}
__device__ __forceinline__ void fsplit(float x, __half& h, __half& l) {
    h = __float2half_rn(x);
    l = __float2half_rn(x - __half2float(h));
}
__device__ __forceinline__ float blk_sum256(float v) {
    __shared__ float red[9];
    int tid = threadIdx.x;
#pragma unroll
    for (int o = 16; o > 0; o >>= 1) v += __shfl_xor_sync(0xffffffffu, v, o);
    if ((tid & 31) == 0) red[tid >> 5] = v;
    __syncthreads();
    if (tid == 0) { float s = 0.f; for (int i = 0; i < 8; i++) s += red[i]; red[8] = s; }
    __syncthreads();
    float s = red[8];
    __syncthreads();
    return s;
}
// 64B-row swizzle (BK=32 pipeline)
__device__ __forceinline__ int swz64(int r, int kh) {
    return r * 64 + ((((kh >> 3) ^ ((r >> 1) & 3))) << 4);
}
// 128B-row swizzle (K resident tiles, DH=64 halfs per row)
__device__ __forceinline__ int swz128(int r, int kh) {
    return r * 128 + ((((kh >> 3) ^ (r & 7))) << 4);
}
// 1024B-row swizzle (probs / V tiles, 512 halfs per row)
__device__ __forceinline__ int swzP(int r, int kh) {
    return r * 1024 + ((((kh >> 3) ^ (r & 7))) << 4) + (kh & 7) * 2;
}

// =====================================================================
// split-fp16 HMMA GEMM, cp.async 3-stage, BK=32: C = alpha*(A B^T + bias)
// MRELM: 0 none; 3 DUAL banded (z<32 c2p from A, z>=32 p2c from A2)
// OUTM: 0 = fp32 C; 1 = split fp16 (Ch,Cl)
// PKPQ: batched all-layer pk/pq — z<L: identity; z>=L: bias[(z-L)*H + n], alpha
// =====================================================================
template<int TM, int TN, bool GELU, bool HASBIAS, int OUTM, int MRELM, bool PKPQ>
__global__ __launch_bounds__(256)
void hgemm(const __half* __restrict__ Ah, const __half* __restrict__ Al, int lda, long sA,
           const __half* __restrict__ Bh, const __half* __restrict__ Bl, int ldb, long sB, int zmodB,
           float* __restrict__ C, __half* __restrict__ Ch, __half* __restrict__ Cl,
           int ldc, long sCo, long sCi, int zmodC,
           const float* __restrict__ bias, float alpha, int K,
           const __half* __restrict__ A2h, const __half* __restrict__ A2l)
{
    constexpr int NS = 3;
    constexpr int WY = (TM == 128) ? 4 : 2;
    constexpr int WN = TN / (8 / WY);
    constexpr int NBLK = WN / 8;
    constexpr int OAH = 0, OAL = TM * 64, OBH = 2 * TM * 64, OBL = 2 * TM * 64 + TN * 64;
    constexpr int STG = (TM + TN) * 128;
    constexpr int CA = TM * 4, CB = TN * 4;
    constexpr int TOT = 2 * (CA + CB);

    extern __shared__ char smraw[];
    const uint32_t smb = (smem_u32(smraw) + 255u) & ~255u;

    const int z = blockIdx.z;
    const bool sec = (MRELM == 3) && (z >= ZBH_);
    const int zz = sec ? z - ZBH_ : z;
    const __half* Ahz = (sec ? A2h : Ah) + (long)zz * sA;
    const __half* Alz = (sec ? A2l : Al) + (long)zz * sA;
    const __half* Bhz = Bh + (sec ? (long)L_*R2_*H_ : 0)
                      + (long)(zmodB ? (zz % zmodB) : zz) * sB;
    const __half* Blz = Bl + (sec ? (long)L_*R2_*H_ : 0)
                      + (long)(zmodB ? (zz % zmodB) : zz) * sB;
    const long coff = zmodC ? ((long)(z / zmodC) * sCo + (long)(z % zmodC) * sCi)
                            : (long)z * sCi;
    const int m0 = blockIdx.y * TM;
    const int n0 = (MRELM == 0) ? blockIdx.x * TN
                 : (sec ? (blockIdx.x * TN + 384 - m0) : (blockIdx.x * TN + m0));
    const int ncb = blockIdx.x * TN;
    const int tid = threadIdx.x, lane = tid & 31, wid = tid >> 5;
    const int wm = (wid % WY) * 32, wn = (wid / WY) * WN;

    float acc[2][NBLK][4];
#pragma unroll
    for (int i = 0; i < 2; i++)
#pragma unroll
        for (int j = 0; j < NBLK; j++)
#pragma unroll
            for (int u = 0; u < 4; u++) acc[i][j][u] = 0.f;

    auto issue_stage = [&](int st, int k0) {
        uint32_t sb = smb + (uint32_t)st * STG;
#pragma unroll
        for (int ii = 0; ii < TOT; ii += 256) {
            int i = ii + tid;
            const __half* src; uint32_t dst;
            if (ii < CA) {
                int r = i >> 2, ch = i & 3;
                src = Ahz + (long)(m0 + r) * lda + k0 + ch * 8;
                dst = OAH + (uint32_t)swz64(r, ch << 3);
            } else if (ii < 2 * CA) {
                int q = i - CA; int r = q >> 2, ch = q & 3;
                src = Alz + (long)(m0 + r) * lda + k0 + ch * 8;
                dst = OAL + (uint32_t)swz64(r, ch << 3);
            } else if (ii < 2 * CA + CB) {
                int q = i - 2 * CA; int r = q >> 2, ch = q & 3;
                src = Bhz + (long)(n0 + r) * ldb + k0 + ch * 8;
                dst = OBH + (uint32_t)swz64(r, ch << 3);
            } else {
                int q = i - 2 * CA - CB; int r = q >> 2, ch = q & 3;
                src = Blz + (long)(n0 + r) * ldb + k0 + ch * 8;
                dst = OBL + (uint32_t)swz64(r, ch << 3);
            }
            cp16(sb + dst, src);
        }
    };

    const int nc = K >> 5;
#pragma unroll
    for (int s = 0; s < NS - 1; s++) {
        if (s < nc) issue_stage(s, s << 5);
        cp_commit();
    }

    for (int c = 0; c < nc; c++) {
        if (c < nc - (NS - 1)) cp_wait<NS - 2>();
        else                   cp_wait<0>();
        __syncthreads();
        int ns = c + NS - 1;
        if (ns < nc) issue_stage(ns % NS, ns << 5);
        cp_commit();

        int bidx = c % NS;
        const uint32_t cb = smb + (uint32_t)bidx * STG;
#pragma unroll
        for (int k16 = 0; k16 < 2; k16++) {
            uint32_t aH[2][4], aL[2][4];
#pragma unroll
            for (int mt = 0; mt < 2; mt++) {
                int r  = wm + mt * 16 + (lane & 15);
                int kh = k16 * 16 + ((lane >> 4) << 3);
                int off = swz64(r, kh);
                ldsm4(aH[mt], cb + OAH + off);
                ldsm4(aL[mt], cb + OAL + off);
            }
            uint32_t bH[NBLK][2], bL[NBLK][2];
#pragma unroll
            for (int nb2 = 0; nb2 < NBLK / 2; nb2++) {
                int r  = wn + nb2 * 16 + ((lane >> 4) << 3) + (lane & 7);
                int kh = k16 * 16 + (((lane >> 3) & 1) << 3);
                int off = swz64(r, kh);
                uint32_t t4[4];
                ldsm4(t4, cb + OBH + off);
                bH[2*nb2][0] = t4[0]; bH[2*nb2][1] = t4[1];
                bH[2*nb2+1][0] = t4[2]; bH[2*nb2+1][1] = t4[3];
                ldsm4(t4, cb + OBL + off);
                bL[2*nb2][0] = t4[0]; bL[2*nb2][1] = t4[1];
                bL[2*nb2+1][0] = t4[2]; bL[2*nb2+1][1] = t4[3];
            }
#pragma unroll
            for (int mt = 0; mt < 2; mt++)
#pragma unroll
                for (int nt = 0; nt < NBLK; nt++) {
                    mma16816(acc[mt][nt], aH[mt], bH[nt]);
                    mma16816(acc[mt][nt], aH[mt], bL[nt]);
                    mma16816(acc[mt][nt], aL[mt], bH[nt]);
                }
        }
    }

    // ---- store ----
#pragma unroll
    for (int mt = 0; mt < 2; mt++)
#pragma unroll
        for (int nt = 0; nt < NBLK; nt++) {
            int m = m0 + wm + mt * 16 + (lane >> 2);
            int nl = wn + nt * 8 + (lane & 3) * 2;
            int n = n0 + nl;
            int nst = (MRELM != 0) ? (ncb + nl) : n;
            float b0, b1, aa;
            if (PKPQ) {
                if (z >= L_) {
                    const float* bz = bias + (long)(z - L_) * H_;
                    b0 = bz[n]; b1 = bz[n + 1]; aa = alpha;
                } else { b0 = 0.f; b1 = 0.f; aa = 1.f; }
            } else {
                b0 = HASBIAS ? bias[n] : 0.f;
                b1 = HASBIAS ? bias[n + 1] : 0.f;
                aa = alpha;
            }
            float x0 = (acc[mt][nt][0] + b0) * aa;
            float x1 = (acc[mt][nt][1] + b1) * aa;
            float x2 = (acc[mt][nt][2] + b0) * aa;
            float x3 = (acc[mt][nt][3] + b1) * aa;
            if (GELU) { x0 = gelu_f(x0); x1 = gelu_f(x1); x2 = gelu_f(x2); x3 = gelu_f(x3); }
            if (OUTM == 0) {
                float* Cb = C + coff;
                *(float2*)(Cb + (long)m * ldc + nst)       = make_float2(x0, x1);
                *(float2*)(Cb + (long)(m + 8) * ldc + nst) = make_float2(x2, x3);
            } else {
                __half* Chb = Ch + coff;
                __half* Clb = Cl + coff;
                __half h0, l0, h1, l1;
                fsplit(x0, h0, l0); fsplit(x1, h1, l1);
                *(__half2*)(Chb + (long)m * ldc + nst) = __halves2half2(h0, h1);
                *(__half2*)(Clb + (long)m * ldc + nst) = __halves2half2(l0, l1);
                fsplit(x2, h0, l0); fsplit(x3, h1, l1);
                *(__half2*)(Chb + (long)(m + 8) * ldc + nst) = __halves2half2(h0, h1);
                *(__half2*)(Clb + (long)(m + 8) * ldc + nst) = __halves2half2(l0, l1);
            }
        }
}

// =====================================================================
// Fused attention: scores + band-add + masked softmax + ctx (probs in smem).
// grid (16, 32): CTA = one (b,h) and 32 q-rows; K staged, then V overwrites K.
// =====================================================================
#define SM_FA 205056
__global__ __launch_bounds__(256) void fused_attn_k(
    const __half* __restrict__ qh_, const __half* __restrict__ ql_,
    const __half* __restrict__ kh_, const __half* __restrict__ kl_,
    const __half* __restrict__ vTh_, const __half* __restrict__ vTl_,
    const float* __restrict__ c2pb, const float* __restrict__ p2cb,
    __half* __restrict__ cxh_, __half* __restrict__ cxl_,
    const int* __restrict__ mask)
{
    extern __shared__ char smraw[];
    __shared__ float sred[32][8];
    __shared__ float grow[32];
    const uint32_t smb = (smem_u32(smraw) + 255u) & ~255u;
    constexpr int OAH = 0, OAL = 4096, OBH = 8192, OBL = 73728;
    constexpr int OPH = 139264, OPL = 172032;

    const int z = blockIdx.y;
    const int bz = z >> 4, h4 = z & 15;
    const int tid = threadIdx.x, lane = tid & 31, wid = tid >> 5;
    const int r0 = lane >> 2;
    const int m0 = blockIdx.x * 32;

    const __half* Ah = qh_ + (long)z * S_ * DH_;
    const __half* Al = ql_ + (long)z * S_ * DH_;
    const __half* Bh = kh_ + (long)z * S_ * DH_;
    const __half* Bl = kl_ + (long)z * S_ * DH_;
    const __half* Vh = vTh_ + (long)z * DH_ * S_;
    const __half* Vl = vTl_ + (long)z * DH_ * S_;

    // ---- stage q tile + all 512 K rows ----
    {
        int r = tid >> 3, ch = tid & 7;
        cp16(smb + OAH + (uint32_t)swz128(r, ch << 3), Ah + (long)(m0 + r) * DH_ + ch * 8);
        cp16(smb + OAL + (uint32_t)swz128(r, ch << 3), Al + (long)(m0 + r) * DH_ + ch * 8);
    }
#pragma unroll
    for (int ii = 0; ii < 16; ii++) {
        int i = ii * 256 + tid;
        int r = i >> 3, ch = i & 7;
        cp16(smb + OBH + (uint32_t)swz128(r, ch << 3), Bh + (long)r * DH_ + ch * 8);
        cp16(smb + OBL + (uint32_t)swz128(r, ch << 3), Bl + (long)r * DH_ + ch * 8);
    }
    cp_commit();
    cp_wait<0>();
    __syncthreads();

    // ---- scores MMA: m=32 (2 tiles), n=512 (8 blocks/warp x 8 warps), K=64 ----
    float acc[2][8][4];
#pragma unroll
    for (int mt = 0; mt < 2; mt++)
#pragma unroll
        for (int nt = 0; nt < 8; nt++)
#pragma unroll
            for (int u = 0; u < 4; u++) acc[mt][nt][u] = 0.f;

#pragma unroll
    for (int k16 = 0; k16 < 4; k16++) {
        uint32_t aH[2][4], aL[2][4];
#pragma unroll
        for (int mt = 0; mt < 2; mt++) {
            int r  = mt * 16 + (lane & 15);
            int kk = k16 * 16 + ((lane >> 4) << 3);
            ldsm4(aH[mt], smb + OAH + swz128(r, kk));
            ldsm4(aL[mt], smb + OAL + swz128(r, kk));
        }
        uint32_t bH[8][2], bL[8][2];
#pragma unroll
        for (int nb2 = 0; nb2 < 4; nb2++) {
            int r  = wid * 64 + nb2 * 16 + ((lane >> 4) << 3) + (lane & 7);
            int kk = k16 * 16 + (((lane >> 3) & 1) << 3);
            uint32_t t4[4];
            ldsm4(t4, smb + OBH + swz128(r, kk));
            bH[2*nb2][0] = t4[0]; bH[2*nb2][1] = t4[1];
            bH[2*nb2+1][0] = t4[2]; bH[2*nb2+1][1] = t4[3];
            ldsm4(t4, smb + OBL + swz128(r, kk));
            bL[2*nb2][0] = t4[0]; bL[2*nb2][1] = t4[1];
            bL[2*nb2+1][0] = t4[2]; bL[2*nb2+1][1] = t4[3];
        }
#pragma unroll
        for (int mt = 0; mt < 2; mt++)
#pragma unroll
            for (int nt = 0; nt < 8; nt++) {
                mma16816(acc[mt][nt], aH[mt], bH[nt]);
                mma16816(acc[mt][nt], aH[mt], bL[nt]);
                mma16816(acc[mt][nt], aL[mt], bH[nt]);
            }
    }
    __syncthreads();   // all K reads complete

    // ---- overlap: stage V (64 rows x 1024B, swzP) over the K region ----
#pragma unroll
    for (int ii = 0; ii < 16; ii++) {
        int i = ii * 256 + tid;             // 4096 chunks per plane
        int r = i >> 6, c = i & 63;
        uint32_t o = (uint32_t)(r * 1024 + (((c ^ (r & 7))) << 4));
        cp16(smb + OBH + o, Vh + (long)r * S_ + c * 8);
        cp16(smb + OBL + o, Vl + (long)r * S_ + c * 8);
    }
    cp_commit();

    // ---- band add + mask; rows owned: q = m0 + r0 + i*8, i = mt*2 + (u>>1) ----
    float mq[4];
#pragma unroll
    for (int i = 0; i < 4; i++)
        mq[i] = (float)mask[bz * S_ + m0 + r0 + i * 8];

    float rmax[4] = {-1e30f, -1e30f, -1e30f, -1e30f};
#pragma unroll
    for (int mt = 0; mt < 2; mt++)
#pragma unroll
        for (int nt = 0; nt < 8; nt++) {
            int nbase = wid * 64 + nt * 8 + (lane & 3) * 2;
#pragma unroll
            for (int u = 0; u < 4; u++) {
                int i = mt * 2 + (u >> 1);
                int q = m0 + r0 + i * 8;
                int n = nbase + (u & 1);
                float x = acc[mt][nt][u]
                    + c2pb[((long)z * S_ + q) * BW_ + (q & 127) + 512 - n]
                    + p2cb[((long)z * S_ + n) * BW_ + q - (n & 127) + 128];
                float w = mq[i] * (float)mask[bz * S_ + n];
                float s = (w > 0.f) ? x : -1e9f;
                acc[mt][nt][u] = s;
                rmax[i] = fmaxf(rmax[i], s);
            }
        }
#pragma unroll
    for (int i = 0; i < 4; i++) {
        rmax[i] = fmaxf(rmax[i], __shfl_xor_sync(0xffffffffu, rmax[i], 1));
        rmax[i] = fmaxf(rmax[i], __shfl_xor_sync(0xffffffffu, rmax[i], 2));
    }
    if ((lane & 3) == 0) {
#pragma unroll
        for (int i = 0; i < 4; i++) sred[r0 + i * 8][wid] = rmax[i];
    }
    __syncthreads();
    if (tid < 32) {
        float m = sred[tid][0];
#pragma unroll
        for (int w8 = 1; w8 < 8; w8++) m = fmaxf(m, sred[tid][w8]);
        grow[tid] = m;
    }
    __syncthreads();
    float gmax[4];
#pragma unroll
    for (int i = 0; i < 4; i++) gmax[i] = grow[r0 + i * 8];
    __syncthreads();

    float rsum[4] = {0.f, 0.f, 0.f, 0.f};
#pragma unroll
    for (int mt = 0; mt < 2; mt++)
#pragma unroll
        for (int nt = 0; nt < 8; nt++)
#pragma unroll
            for (int u = 0; u < 4; u++) {
                int i = mt * 2 + (u >> 1);
                float e = __expf(acc[mt][nt][u] - gmax[i]);
                acc[mt][nt][u] = e;
                rsum[i] += e;
            }
#pragma unroll
    for (int i = 0; i < 4; i++) {
        rsum[i] += __shfl_xor_sync(0xffffffffu, rsum[i], 1);
        rsum[i] += __shfl_xor_sync(0xffffffffu, rsum[i], 2);
    }
    if ((lane & 3) == 0) {
#pragma unroll
        for (int i = 0; i < 4; i++) sred[r0 + i * 8][wid] = rsum[i];
    }
    __syncthreads();
    if (tid < 32) {
        float s = 0.f;
#pragma unroll
        for (int w8 = 0; w8 < 8; w8++) s += sred[tid][w8];
        grow[tid] = 1.0f / s;
    }
    __syncthreads();
    float ginv[4];
#pragma unroll
    for (int i = 0; i < 4; i++) ginv[i] = grow[r0 + i * 8];

    // ---- write split-fp16 probs to SMEM (swzP, local rows lq in [0,32)) ----
#pragma unroll
    for (int mt = 0; mt < 2; mt++)
#pragma unroll
        for (int nt = 0; nt < 8; nt++) {
            int nbase = wid * 64 + nt * 8 + (lane & 3) * 2;
            float mk0 = (float)mask[bz * S_ + nbase];
            float mk1 = (float)mask[bz * S_ + nbase + 1];
            int i0 = mt * 2, i1 = mt * 2 + 1;
            int lq0 = r0 + i0 * 8, lq1 = r0 + i1 * 8;
            float p0 = acc[mt][nt][0] * ginv[i0] * (mq[i0] * mk0);
            float p1 = acc[mt][nt][1] * ginv[i0] * (mq[i0] * mk1);
            float p2 = acc[mt][nt][2] * ginv[i1] * (mq[i1] * mk0);
            float p3 = acc[mt][nt][3] * ginv[i1] * (mq[i1] * mk1);
            __half h0, l0, h1, l1;
            uint32_t o0 = (uint32_t)swzP(lq0, nbase);
            uint32_t o1 = (uint32_t)swzP(lq1, nbase);
            fsplit(p0, h0, l0); fsplit(p1, h1, l1);
            *(__half2*)(smraw + ((smb + OPH + o0) - smem_u32(smraw))) = __halves2half2(h0, h1);
            *(__half2*)(smraw + ((smb + OPL + o0) - smem_u32(smraw))) = __halves2half2(l0, l1);
            fsplit(p2, h0, l0); fsplit(p3, h1, l1);
            *(__half2*)(smraw + ((smb + OPH + o1) - smem_u32(smraw))) = __halves2half2(h0, h1);
            *(__half2*)(smraw + ((smb + OPL + o1) - smem_u32(smraw))) = __halves2half2(l0, l1);
        }
    cp_wait<0>();
    __syncthreads();   // probs visible + V loaded

    // ---- ctx MMA: warps 2(m16) x 4(n16); A = probs (smem), B = V (smem) ----
    const int mw = (wid & 1) * 16, nw = (wid >> 1) * 16;
    float acc2[2][4];
#pragma unroll
    for (int nt = 0; nt < 2; nt++)
#pragma unroll
        for (int u = 0; u < 4; u++) acc2[nt][u] = 0.f;

#pragma unroll 4
    for (int k16 = 0; k16 < 32; k16++) {
        uint32_t aH[4], aL[4];
        int ar  = mw + (lane & 15);
        int akh = k16 * 16 + ((lane >> 4) << 3);
        uint32_t aoff = (uint32_t)(ar * 1024 + ((((akh >> 3) ^ (ar & 7))) << 4));
        ldsm4(aH, smb + OPH + aoff);
        ldsm4(aL, smb + OPL + aoff);
        uint32_t bH[4], bL[4];
        int br  = nw + ((lane >> 4) << 3) + (lane & 7);
        int bkh = k16 * 16 + (((lane >> 3) & 1) << 3);
        uint32_t boff = (uint32_t)(br * 1024 + ((((bkh >> 3) ^ (br & 7))) << 4));
        ldsm4(bH, smb + OBH + boff);
        ldsm4(bL, smb + OBL + boff);
        mma16816(acc2[0], aH, bH + 0); mma16816(acc2[0], aH, bL + 0); mma16816(acc2[0], aL, bH + 0);
        mma16816(acc2[1], aH, bH + 2); mma16816(acc2[1], aH, bL + 2); mma16816(acc2[1], aL, bH + 2);
    }

    // ---- write ctx split-fp16: [b*S+q][h4*64 + n] ----
#pragma unroll
    for (int nt = 0; nt < 2; nt++) {
        int q = m0 + mw + (lane >> 2);
        int n = nw + nt * 8 + (lane & 3) * 2;
        long o = ((long)(bz * S_ + q)) * H_ + h4 * 64 + n;
        __half h0, l0, h1, l1;
        fsplit(acc2[nt][0], h0, l0); fsplit(acc2[nt][1], h1, l1);
        *(__half2*)(cxh_ + o) = __halves2half2(h0, h1);
        *(__half2*)(cxl_ + o) = __halves2half2(l0, l1);
        fsplit(acc2[nt][2], h0, l0); fsplit(acc2[nt][3], h1, l1);
        *(__half2*)(cxh_ + o + 8 * H_) = __halves2half2(h0, h1);
        *(__half2*)(cxl_ + o + 8 * H_) = __halves2half2(l0, l1);
    }
}

// ---------------- bulk fp32 -> split fp16 conversion ----------------
__global__ __launch_bounds__(256) void cvt_split_k(const float* __restrict__ x,
        __half* __restrict__ h, __half* __restrict__ l, int n4)
{
    int i = blockIdx.x * 256 + threadIdx.x;
    if (i >= n4) return;
    float4 v = *(const float4*)(x + 4 * (long)i);
    __half h0,l0,h1,l1,h2,l2,h3,l3;
    fsplit(v.x,h0,l0); fsplit(v.y,h1,l1); fsplit(v.z,h2,l2); fsplit(v.w,h3,l3);
    __half2 ha = __halves2half2(h0,h1), hb = __halves2half2(h2,h3);
    __half2 la = __halves2half2(l0,l1), lb = __halves2half2(l2,l3);
    uint2 hu, lu;
    hu.x = *(uint32_t*)&ha; hu.y = *(uint32_t*)&hb;
    lu.x = *(uint32_t*)&la; lu.y = *(uint32_t*)&lb;
    *(uint2*)(h + 4 * (long)i) = hu;
    *(uint2*)(l + 4 * (long)i) = lu;
}

// ---------------- split qkv -> split-fp16 q,k [b,h,s,d], vT [b,h,d,s] ----------------
__global__ void split_qkv_k(const float* __restrict__ qkv,
                            const float* __restrict__ qb,
                            const float* __restrict__ vb, float inv_scale)
{
    int idx = blockIdx.x * 256 + threadIdx.x;
    int d = idx & 63, h = (idx >> 6) & 15, s = (idx >> 10) & 511, b = idx >> 19;
    long base = (long)(b * S_ + s) * 3 * H_ + h * 3 * DH_;
    int o  = ((b * NH_ + h) * S_ + s) * DH_ + d;
    int ot = ((b * NH_ + h) * DH_ + d) * S_ + s;
    __half hh, ll;
    fsplit((qkv[base + d] + qb[h * DH_ + d]) * inv_scale, hh, ll);
    g_qh[o] = hh; g_ql[o] = ll;
    fsplit(qkv[base + DH_ + d], hh, ll);
    g_kh[o] = hh; g_kl[o] = ll;
    fsplit(qkv[base + 2 * DH_ + d] + vb[h * DH_ + d], hh, ll);
    g_vTh[ot] = hh; g_vTl[ot] = ll;
}

// ---------------- h = LN(h + delta), emits fp32 h and split fp16 ----------------
__global__ __launch_bounds__(256) void add_ln_k(float* __restrict__ hb,
        const float* __restrict__ dl, const float* __restrict__ sc,
        const float* __restrict__ bc, float eps)
{
    long t = blockIdx.x;
    float* x = hb + t * H_;
    const float* d = dl + t * H_;
    int tid = threadIdx.x;
    float v[4]; float ls = 0.f;
#pragma unroll
    for (int j = 0; j < 4; j++) { int i = tid + (j << 8); v[j] = x[i] + d[i]; ls += v[j]; }
    float mu = blk_sum256(ls) * (1.0f / H_);
    float lv = 0.f;
#pragma unroll
    for (int j = 0; j < 4; j++) { float dd = v[j] - mu; lv += dd * dd; }
    float var = blk_sum256(lv) * (1.0f / H_);
    float rstd = rsqrtf(var + eps);
#pragma unroll
    for (int j = 0; j < 4; j++) {
        int i = tid + (j << 8);
        float y = (v[j] - mu) * rstd * sc[i] + bc[i];
        x[i] = y;
        __half hh, ll; fsplit(y, hh, ll);
        g_hh[t * H_ + i] = hh; g_hl[t * H_ + i] = ll;
    }
}

// ---------------- embedding gather + LN * mask ----------------
__global__ __launch_bounds__(256) void embed_k(const int* __restrict__ ids,
        const int* __restrict__ mask, const float* __restrict__ we,
        const float* __restrict__ s, const float* __restrict__ bb)
{
    int t = blockIdx.x;
    long ro = (long)ids[t] * H_;
    float mf = (float)mask[t];
    int tid = threadIdx.x;
    float v[4]; float ls = 0.f;
#pragma unroll
    for (int j = 0; j < 4; j++) { v[j] = we[ro + tid + (j << 8)]; ls += v[j]; }
    float mu = blk_sum256(ls) * (1.0f / H_);
    float lv = 0.f;
#pragma unroll
    for (int j = 0; j < 4; j++) { float dd = v[j] - mu; lv += dd * dd; }
    float var = blk_sum256(lv) * (1.0f / H_);
    float rstd = rsqrtf(var + 1e-7f);
#pragma unroll
    for (int j = 0; j < 4; j++) {
        int i = tid + (j << 8);
        float y = ((v[j] - mu) * rstd * s[i] + bb[i]) * mf;
        g_h[(long)t * H_ + i] = y;
        __half hh, ll; fsplit(y, hh, ll);
        g_hh[(long)t * H_ + i] = hh; g_hl[(long)t * H_ + i] = ll;
    }
}

// ---------------- head ----------------
__global__ __launch_bounds__(256) void head_k(const float* __restrict__ hb,
        const float* __restrict__ s, const float* __restrict__ bb,
        const float* __restrict__ ow, const float* __restrict__ ob,
        float* __restrict__ out)
{
    int b = blockIdx.x;
    const float* x = hb + (long)b * S_ * H_;
    int tid = threadIdx.x;
    float v[4]; float ls = 0.f;
#pragma unroll
    for (int j = 0; j < 4; j++) { v[j] = x[tid + (j << 8)]; ls += v[j]; }
    float mu = blk_sum256(ls) * (1.0f / H_);
    float lv = 0.f;
#pragma unroll
    for (int j = 0; j < 4; j++) { float dd = v[j] - mu; lv += dd * dd; }
    float var = blk_sum256(lv) * (1.0f / H_);
    float rstd = rsqrtf(var + 1e-5f);
    float ld = 0.f;
#pragma unroll
    for (int j = 0; j < 4; j++) {
        int i = tid + (j << 8);
        float y = (v[j] - mu) * rstd * s[i] + bb[i];
        ld += y * ow[i];
    }
    float dot = blk_sum256(ld);
    if (tid == 0) out[b] = dot + ob[0];
}

// ---------------- host orchestration ----------------
#define SM_128_128 98560
#define SM_128_64  73984
#define SM_64_64   49408

extern "C" void kernel_launch(void* const* d_in, const int* in_sizes, int n_in,
                              void* d_out, int out_size)
{
    const int*   ids       = (const int*)  d_in[0];
    const int*   mask      = (const int*)  d_in[1];
    const float* word_emb  = (const float*)d_in[3];
    const float* emb_ln_s  = (const float*)d_in[4];
    const float* emb_ln_b  = (const float*)d_in[5];
    const float* rel_emb   = (const float*)d_in[6];
    const float* in_w      = (const float*)d_in[7];
    const float* q_bias    = (const float*)d_in[8];
    const float* v_bias    = (const float*)d_in[9];
    const float* pos_k_w   = (const float*)d_in[10];
    const float* pos_q_w   = (const float*)d_in[11];
    const float* pos_q_b   = (const float*)d_in[12];
    const float* attn_o_w  = (const float*)d_in[13];
    const float* attn_o_b  = (const float*)d_in[14];
    const float* ln1_s     = (const float*)d_in[15];
    const float* ln1_b     = (const float*)d_in[16];
    const float* ffn_w1    = (const float*)d_in[17];
    const float* ffn_b1    = (const float*)d_in[18];
    const float* ffn_w2    = (const float*)d_in[19];
    const float* ffn_b2    = (const float*)d_in[20];
    const float* ln2_s     = (const float*)d_in[21];
    const float* ln2_b     = (const float*)d_in[22];
    const float* head_ln_s = (const float*)d_in[23];
    const float* head_ln_b = (const float*)d_in[24];
    const float* out_w     = (const float*)d_in[25];
    const float* out_b     = (const float*)d_in[26];
    float* out = (float*)d_out;

    float *h_, *qkv_, *band_, *t2_;
    cudaGetSymbolAddress((void**)&h_,   g_h);
    cudaGetSymbolAddress((void**)&qkv_, g_qkv);
    cudaGetSymbolAddress((void**)&band_,g_band);
    cudaGetSymbolAddress((void**)&t2_,  g_t2);
    float* c2p_ = band_;
    float* p2c_ = band_ + (size_t)ZBH_ * S_ * BW_;

    __half *wih,*wil,*ppwh,*ppwl,*aowh,*aowl,*w1h,*w1l,*w2h,*w2l,*relh,*rell;
    cudaGetSymbolAddress((void**)&wih,  g_wih);  cudaGetSymbolAddress((void**)&wil,  g_wil);
    cudaGetSymbolAddress((void**)&ppwh, g_ppwh); cudaGetSymbolAddress((void**)&ppwl, g_ppwl);
    cudaGetSymbolAddress((void**)&aowh, g_aowh); cudaGetSymbolAddress((void**)&aowl, g_aowl);
    cudaGetSymbolAddress((void**)&w1h,  g_w1h);  cudaGetSymbolAddress((void**)&w1l,  g_w1l);
    cudaGetSymbolAddress((void**)&w2h,  g_w2h);  cudaGetSymbolAddress((void**)&w2l,  g_w2l);
    cudaGetSymbolAddress((void**)&relh, g_relh); cudaGetSymbolAddress((void**)&rell, g_rell);

    __half *hh,*hl,*qh,*ql,*kh,*kl,*vTh,*vTl,*ppoh,*ppol,*cxh,*cxl,*ffh,*ffl;
    cudaGetSymbolAddress((void**)&hh,  g_hh);  cudaGetSymbolAddress((void**)&hl,  g_hl);
    cudaGetSymbolAddress((void**)&qh,  g_qh);  cudaGetSymbolAddress((void**)&ql,  g_ql);
    cudaGetSymbolAddress((void**)&kh,  g_kh);  cudaGetSymbolAddress((void**)&kl,  g_kl);
    cudaGetSymbolAddress((void**)&vTh, g_vTh); cudaGetSymbolAddress((void**)&vTl, g_vTl);
    cudaGetSymbolAddress((void**)&ppoh,g_ppoh);cudaGetSymbolAddress((void**)&ppol,g_ppol);
    cudaGetSymbolAddress((void**)&cxh, g_cxh); cudaGetSymbolAddress((void**)&cxl, g_cxl);
    cudaGetSymbolAddress((void**)&ffh, g_ffh); cudaGetSymbolAddress((void**)&ffl, g_ffl);

    cudaFuncSetAttribute(hgemm<128,64 ,false,false,0,0,false>, cudaFuncAttributeMaxDynamicSharedMemorySize, SM_128_64);
    cudaFuncSetAttribute(hgemm<128,64 ,true ,true ,1,0,false>, cudaFuncAttributeMaxDynamicSharedMemorySize, SM_128_64);
    cudaFuncSetAttribute(hgemm<128,128,false,false,0,3,false>, cudaFuncAttributeMaxDynamicSharedMemorySize, SM_128_128);
    cudaFuncSetAttribute(hgemm<64 ,64 ,false,true ,1,0,true >, cudaFuncAttributeMaxDynamicSharedMemorySize, SM_64_64);
    cudaFuncSetAttribute(hgemm<64 ,64 ,false,true ,0,0,false>, cudaFuncAttributeMaxDynamicSharedMemorySize, SM_64_64);
    cudaFuncSetAttribute(fused_attn_k, cudaFuncAttributeMaxDynamicSharedMemorySize, SM_FA);

    const float inv_scale = 1.0f / sqrtf(3.0f * DH_);

    // ---- weight conversion ----
    cvt_split_k<<<(NIW/4 + 255)/256, 256>>>(in_w,     wih,  wil,  NIW/4);
    cvt_split_k<<<(NPW/4 + 255)/256, 256>>>(pos_k_w,  ppwh,       ppwl,       NPW/4);
    cvt_split_k<<<(NPW/4 + 255)/256, 256>>>(pos_q_w,  ppwh + NPW, ppwl + NPW, NPW/4);
    cvt_split_k<<<(NPW/4 + 255)/256, 256>>>(attn_o_w, aowh, aowl, NPW/4);
    cvt_split_k<<<(NW1/4 + 255)/256, 256>>>(ffn_w1,   w1h,  w1l,  NW1/4);
    cvt_split_k<<<(NW1/4 + 255)/256, 256>>>(ffn_w2,   w2h,  w2l,  NW1/4);
    cvt_split_k<<<(R2_*H_/4 + 255)/256, 256>>>(rel_emb, relh, rell, R2_*H_/4);

    embed_k<<<BS_, 256>>>(ids, mask, word_emb, emb_ln_s, emb_ln_b);

    // ---- ALL layers' pk (z<12) / pq (z>=12) in one batched launch ----
    hgemm<64,64,false,true,1,0,true><<<dim3(16, 16, 2*L_), 256, SM_64_64>>>(
        relh, rell, H_, 0, ppwh, ppwl, H_, (long)H_*H_, 0,
        nullptr, ppoh, ppol, H_, 0, (long)R2_*H_, 0,
        pos_q_b, inv_scale, H_, nullptr, nullptr);

    for (int l = 0; l < L_; l++) {
        // qkv = h @ in_w^T -> fp32
        hgemm<128,64,false,false,0,0,false><<<dim3(48, 8, 1), 256, SM_128_64>>>(
            hh, hl, H_, 0, wih + (long)l*3*H_*H_, wil + (long)l*3*H_*H_, H_, 0, 0,
            qkv_, nullptr, nullptr, 3*H_, 0, 0, 0, nullptr, 1.f, H_,
            nullptr, nullptr);
        split_qkv_k<<<(B_*S_*H_)/256, 256>>>(qkv_, q_bias + l*H_, v_bias + l*H_, inv_scale);

        // DUAL banded: z<32 c2p = q @ pk_l^T; z>=32 p2c = k @ pq_l^T
        hgemm<128,128,false,false,0,3,false><<<dim3(5, 4, 2*ZBH_), 256, SM_128_128>>>(
            qh, ql, DH_, (long)S_*DH_,
            ppoh + (long)l*R2_*H_, ppol + (long)l*R2_*H_, H_, DH_, NH_,
            band_, nullptr, nullptr, BW_, 0, (long)S_*BW_, 0,
            nullptr, 1.f, DH_, kh, kl);

        // fused scores + band + softmax + ctx -> split-fp16 ctx
        fused_attn_k<<<dim3(16, 32), 256, SM_FA>>>(
            qh, ql, kh, kl, vTh, vTl, c2p_, p2c_, cxh, cxl, mask);

        // attn out proj -> fp32 t2; residual LN
        hgemm<64,64,false,true,0,0,false><<<dim3(16, 16, 1), 256, SM_64_64>>>(
            cxh, cxl, H_, 0, aowh + (long)l*H_*H_, aowl + (long)l*H_*H_, H_, 0, 0,
            t2_, nullptr, nullptr, H_, 0, 0, 0, attn_o_b + l*H_, 1.f, H_,
            nullptr, nullptr);
        add_ln_k<<<BS_, 256>>>(h_, t2_, ln1_s + l*H_, ln1_b + l*H_, LN_EPS_);

        // FFN
        hgemm<128,64,true,true,1,0,false><<<dim3(64, 8, 1), 256, SM_128_64>>>(
            hh, hl, H_, 0, w1h + (long)l*FF_*H_, w1l + (long)l*FF_*H_, H_, 0, 0,
            nullptr, ffh, ffl, FF_, 0, 0, 0, ffn_b1 + l*FF_, 1.f, H_,
            nullptr, nullptr);
        hgemm<64,64,false,true,0,0,false><<<dim3(16, 16, 1), 256, SM_64_64>>>(
            ffh, ffl, FF_, 0, w2h + (long)l*H_*FF_, w2l + (long)l*H_*FF_, FF_, 0, 0,
            t2_, nullptr, nullptr, H_, 0, 0, 0, ffn_b2 + l*H_, 1.f, FF_,
            nullptr, nullptr);
        add_ln_k<<<BS_, 256>>>(h_, t2_, ln2_s + l*H_, ln2_b + l*H_, LN_EPS_);
    }

    head_k<<<B_, 256>>>(h_, head_ln_s, head_ln_b, out_w, out_b, out);
}

// round 17
// speedup vs baseline: 1.0234x; 1.0234x over previous
#include <cuda_runtime.h>
#include <cuda_fp16.h>
#include <math.h>
#include <stdint.h>

// ---------------- problem constants ----------------
#define B_   2
#define S_   512
#define L_   12
#define H_   1024
#define NH_  16
#define DH_  64
#define FF_  4096
#define R2_  1024          // 2*SPAN
#define BS_  (B_*S_)       // 1024
#define BW_  640           // band width for c2p/p2c
#define ZBH_ (B_*NH_)      // 32
#define LN_EPS_ 1e-7f

// ---------------- fp32 scratch ----------------
__device__ float g_h   [BS_*H_];
__device__ float g_qkv [BS_*3*H_];
__device__ float g_band[(size_t)2*B_*NH_*S_*BW_];  // [c2p(32) | p2c(32)] banded
__device__ float g_t2  [BS_*H_];

// ---------------- fp16 split weight buffers ----------------
#define NIW  (L_*3*H_*H_)
#define NPW  (L_*H_*H_)
#define NW1  (L_*FF_*H_)
__device__ __half g_wih [NIW], g_wil [NIW];
__device__ __half g_ppwh[2*NPW], g_ppwl[2*NPW];   // [0][l]=pos_k_w, [1][l]=pos_q_w
__device__ __half g_aowh[NPW], g_aowl[NPW];
__device__ __half g_w1h [NW1], g_w1l [NW1];
__device__ __half g_w2h [NW1], g_w2l [NW1];
__device__ __half g_relh[R2_*H_], g_rell[R2_*H_];

// ---------------- fp16 split activation buffers ----------------
__device__ __half g_hh [BS_*H_], g_hl [BS_*H_];
__device__ __half g_qh [BS_*H_], g_ql [BS_*H_];
__device__ __half g_kh [BS_*H_], g_kl [BS_*H_];
__device__ __half g_vTh[BS_*H_], g_vTl[BS_*H_];
__device__ __half g_ppoh[(size_t)2*L_*R2_*H_], g_ppol[(size_t)2*L_*R2_*H_];  // [which][l][R2*H]
__device__ __half g_ph [(size_t)B_*NH_*S_*S_], g_pl [(size_t)B_*NH_*S_*S_];
__device__ __half g_cxh[BS_*H_], g_cxl[BS_*H_];
__device__ __half g_ffh[BS_*FF_], g_ffl[BS_*FF_];

// ---------------- asm helpers ----------------
__device__ __forceinline__ uint32_t smem_u32(const void* p) {
    uint32_t a;
    asm("{ .reg .u64 t; cvta.to.shared.u64 t, %1; cvt.u32.u64 %0, t; }"
        : "=r"(a) : "l"(p));
    return a;
}
__device__ __forceinline__ void cp16(uint32_t dst, const void* src) {
    asm volatile("cp.async.cg.shared.global [%0], [%1], 16;" :: "r"(dst), "l"(src));
}
__device__ __forceinline__ void cp_commit() {
    asm volatile("cp.async.commit_group;" ::: "memory");
}
template<int N> __device__ __forceinline__ void cp_wait() {
    asm volatile("cp.async.wait_group %0;" :: "n"(N) : "memory");
}
__device__ __forceinline__ void ldsm4(uint32_t* d, uint32_t a) {
    asm volatile("ldmatrix.sync.aligned.m8n8.x4.shared.b16 {%0,%1,%2,%3}, [%4];"
        : "=r"(d[0]), "=r"(d[1]), "=r"(d[2]), "=r"(d[3]) : "r"(a));
}
__device__ __forceinline__ void mma16816(float* c, const uint32_t* a, const uint32_t* b) {
    asm volatile(
        "mma.sync.aligned.m16n8k16.row.col.f32.f16.f16.f32 "
        "{%0,%1,%2,%3}, {%4,%5,%6,%7}, {%8,%9}, {%0,%1,%2,%3};"
        : "+f"(c[0]), "+f"(c[1]), "+f"(c[2]), "+f"(c[3])
        : "r"(a[0]), "r"(a[1]), "r"(a[2]), "r"(a[3]), "r"(b[0]), "r"(b[1]));
}
__device__ __forceinline__ float gelu_f(float x) {
    float t = tanhf(0.7978845608028654f * (x + 0.044715f * x * x * x));
    return 0.5f * x * (1.0f + t);
}
__device__ __forceinline__ void fsplit(float x, __half& h, __half& l) {
    h = __float2half_rn(x);
    l = __float2half_rn(x - __half2float(h));
}
__device__ __forceinline__ float blk_sum256(float v) {
    __shared__ float red[9];
    int tid = threadIdx.x;
#pragma unroll
    for (int o = 16; o > 0; o >>= 1) v += __shfl_xor_sync(0xffffffffu, v, o);
    if ((tid & 31) == 0) red[tid >> 5] = v;
    __syncthreads();
    if (tid == 0) { float s = 0.f; for (int i = 0; i < 8; i++) s += red[i]; red[8] = s; }
    __syncthreads();
    float s = red[8];
    __syncthreads();
    return s;
}
// 64B-row swizzle (BK=32 pipeline)
__device__ __forceinline__ int swz64(int r, int kh) {
    return r * 64 + ((((kh >> 3) ^ ((r >> 1) & 3))) << 4);
}
// 128B-row swizzle (K=64 resident tiles in fused kernel)
__device__ __forceinline__ int swz128(int r, int kh) {
    return r * 128 + ((((kh >> 3) ^ (r & 7))) << 4);
}

// =====================================================================
// split-fp16 HMMA GEMM, cp.async 3-stage, BK=32: C = alpha*(A B^T + bias)
// MRELM: 0 none; 3 DUAL banded (z<32 c2p from A, z>=32 p2c from A2)
// OUTM: 0 = fp32 C; 1 = split fp16 (Ch,Cl)
// PKPQ: batched all-layer pk/pq — z<L: identity; z>=L: bias[(z-L)*H + n], alpha
// =====================================================================
template<int TM, int TN, bool GELU, bool HASBIAS, int OUTM, int MRELM, bool PKPQ>
__global__ __launch_bounds__(256)
void hgemm(const __half* __restrict__ Ah, const __half* __restrict__ Al, int lda, long sA,
           const __half* __restrict__ Bh, const __half* __restrict__ Bl, int ldb, long sB, int zmodB,
           float* __restrict__ C, __half* __restrict__ Ch, __half* __restrict__ Cl,
           int ldc, long sCo, long sCi, int zmodC,
           const float* __restrict__ bias, float alpha, int K,
           const __half* __restrict__ A2h, const __half* __restrict__ A2l)
{
    constexpr int NS = 3;
    constexpr int WY = (TM == 128) ? 4 : 2;
    constexpr int WN = TN / (8 / WY);
    constexpr int NBLK = WN / 8;
    constexpr int OAH = 0, OAL = TM * 64, OBH = 2 * TM * 64, OBL = 2 * TM * 64 + TN * 64;
    constexpr int STG = (TM + TN) * 128;
    constexpr int CA = TM * 4, CB = TN * 4;
    constexpr int TOT = 2 * (CA + CB);

    extern __shared__ char smraw[];
    const uint32_t smb = (smem_u32(smraw) + 255u) & ~255u;

    const int z = blockIdx.z;
    const bool sec = (MRELM == 3) && (z >= ZBH_);
    const int zz = sec ? z - ZBH_ : z;
    const __half* Ahz = (sec ? A2h : Ah) + (long)zz * sA;
    const __half* Alz = (sec ? A2l : Al) + (long)zz * sA;
    const __half* Bhz = Bh + (sec ? (long)L_*R2_*H_ : 0)
                      + (long)(zmodB ? (zz % zmodB) : zz) * sB;
    const __half* Blz = Bl + (sec ? (long)L_*R2_*H_ : 0)
                      + (long)(zmodB ? (zz % zmodB) : zz) * sB;
    const long coff = zmodC ? ((long)(z / zmodC) * sCo + (long)(z % zmodC) * sCi)
                            : (long)z * sCi;
    const int m0 = blockIdx.y * TM;
    const int n0 = (MRELM == 0) ? blockIdx.x * TN
                 : (sec ? (blockIdx.x * TN + 384 - m0) : (blockIdx.x * TN + m0));
    const int ncb = blockIdx.x * TN;
    const int tid = threadIdx.x, lane = tid & 31, wid = tid >> 5;
    const int wm = (wid % WY) * 32, wn = (wid / WY) * WN;

    float acc[2][NBLK][4];
#pragma unroll
    for (int i = 0; i < 2; i++)
#pragma unroll
        for (int j = 0; j < NBLK; j++)
#pragma unroll
            for (int u = 0; u < 4; u++) acc[i][j][u] = 0.f;

    auto issue_stage = [&](int st, int k0) {
        uint32_t sb = smb + (uint32_t)st * STG;
#pragma unroll
        for (int ii = 0; ii < TOT; ii += 256) {
            int i = ii + tid;
            const __half* src; uint32_t dst;
            if (ii < CA) {
                int r = i >> 2, ch = i & 3;
                src = Ahz + (long)(m0 + r) * lda + k0 + ch * 8;
                dst = OAH + (uint32_t)swz64(r, ch << 3);
            } else if (ii < 2 * CA) {
                int q = i - CA; int r = q >> 2, ch = q & 3;
                src = Alz + (long)(m0 + r) * lda + k0 + ch * 8;
                dst = OAL + (uint32_t)swz64(r, ch << 3);
            } else if (ii < 2 * CA + CB) {
                int q = i - 2 * CA; int r = q >> 2, ch = q & 3;
                src = Bhz + (long)(n0 + r) * ldb + k0 + ch * 8;
                dst = OBH + (uint32_t)swz64(r, ch << 3);
            } else {
                int q = i - 2 * CA - CB; int r = q >> 2, ch = q & 3;
                src = Blz + (long)(n0 + r) * ldb + k0 + ch * 8;
                dst = OBL + (uint32_t)swz64(r, ch << 3);
            }
            cp16(sb + dst, src);
        }
    };

    const int nc = K >> 5;
#pragma unroll
    for (int s = 0; s < NS - 1; s++) {
        if (s < nc) issue_stage(s, s << 5);
        cp_commit();
    }

    for (int c = 0; c < nc; c++) {
        if (c < nc - (NS - 1)) cp_wait<NS - 2>();
        else                   cp_wait<0>();
        __syncthreads();
        int ns = c + NS - 1;
        if (ns < nc) issue_stage(ns % NS, ns << 5);
        cp_commit();

        int bidx = c % NS;
        const uint32_t cb = smb + (uint32_t)bidx * STG;
#pragma unroll
        for (int k16 = 0; k16 < 2; k16++) {
            uint32_t aH[2][4], aL[2][4];
#pragma unroll
            for (int mt = 0; mt < 2; mt++) {
                int r  = wm + mt * 16 + (lane & 15);
                int kh = k16 * 16 + ((lane >> 4) << 3);
                int off = swz64(r, kh);
                ldsm4(aH[mt], cb + OAH + off);
                ldsm4(aL[mt], cb + OAL + off);
            }
            uint32_t bH[NBLK][2], bL[NBLK][2];
#pragma unroll
            for (int nb2 = 0; nb2 < NBLK / 2; nb2++) {
                int r  = wn + nb2 * 16 + ((lane >> 4) << 3) + (lane & 7);
                int kh = k16 * 16 + (((lane >> 3) & 1) << 3);
                int off = swz64(r, kh);
                uint32_t t4[4];
                ldsm4(t4, cb + OBH + off);
                bH[2*nb2][0] = t4[0]; bH[2*nb2][1] = t4[1];
                bH[2*nb2+1][0] = t4[2]; bH[2*nb2+1][1] = t4[3];
                ldsm4(t4, cb + OBL + off);
                bL[2*nb2][0] = t4[0]; bL[2*nb2][1] = t4[1];
                bL[2*nb2+1][0] = t4[2]; bL[2*nb2+1][1] = t4[3];
            }
#pragma unroll
            for (int mt = 0; mt < 2; mt++)
#pragma unroll
                for (int nt = 0; nt < NBLK; nt++) {
                    mma16816(acc[mt][nt], aH[mt], bH[nt]);
                    mma16816(acc[mt][nt], aH[mt], bL[nt]);
                    mma16816(acc[mt][nt], aL[mt], bH[nt]);
                }
        }
    }

    // ---- store ----
#pragma unroll
    for (int mt = 0; mt < 2; mt++)
#pragma unroll
        for (int nt = 0; nt < NBLK; nt++) {
            int m = m0 + wm + mt * 16 + (lane >> 2);
            int nl = wn + nt * 8 + (lane & 3) * 2;
            int n = n0 + nl;
            int nst = (MRELM != 0) ? (ncb + nl) : n;
            float b0, b1, aa;
            if (PKPQ) {
                if (z >= L_) {
                    const float* bz = bias + (long)(z - L_) * H_;
                    b0 = bz[n]; b1 = bz[n + 1]; aa = alpha;
                } else { b0 = 0.f; b1 = 0.f; aa = 1.f; }
            } else {
                b0 = HASBIAS ? bias[n] : 0.f;
                b1 = HASBIAS ? bias[n + 1] : 0.f;
                aa = alpha;
            }
            float x0 = (acc[mt][nt][0] + b0) * aa;
            float x1 = (acc[mt][nt][1] + b1) * aa;
            float x2 = (acc[mt][nt][2] + b0) * aa;
            float x3 = (acc[mt][nt][3] + b1) * aa;
            if (GELU) { x0 = gelu_f(x0); x1 = gelu_f(x1); x2 = gelu_f(x2); x3 = gelu_f(x3); }
            if (OUTM == 0) {
                float* Cb = C + coff;
                *(float2*)(Cb + (long)m * ldc + nst)       = make_float2(x0, x1);
                *(float2*)(Cb + (long)(m + 8) * ldc + nst) = make_float2(x2, x3);
            } else {
                __half* Chb = Ch + coff;
                __half* Clb = Cl + coff;
                __half h0, l0, h1, l1;
                fsplit(x0, h0, l0); fsplit(x1, h1, l1);
                *(__half2*)(Chb + (long)m * ldc + nst) = __halves2half2(h0, h1);
                *(__half2*)(Clb + (long)m * ldc + nst) = __halves2half2(l0, l1);
                fsplit(x2, h0, l0); fsplit(x3, h1, l1);
                *(__half2*)(Chb + (long)(m + 8) * ldc + nst) = __halves2half2(h0, h1);
                *(__half2*)(Clb + (long)(m + 8) * ldc + nst) = __halves2half2(l0, l1);
            }
        }
}

// =====================================================================
// Fused scores + band-add + masked softmax: emits split-fp16 probs.
// grid (8, 32): CTA handles 2 q-tiles of 32 rows x all 512 k-cols for one (b,h).
// K=64, k tiles resident in smem (hi+lo, 128 KB); q tile prefetched during softmax.
// =====================================================================
#define SM_FA 139520
__global__ __launch_bounds__(256) void fused_sm_k(
    const __half* __restrict__ qh_, const __half* __restrict__ ql_,
    const __half* __restrict__ kh_, const __half* __restrict__ kl_,
    const float* __restrict__ c2pb, const float* __restrict__ p2cb,
    __half* __restrict__ ph_, __half* __restrict__ pl_,
    const int* __restrict__ mask)
{
    extern __shared__ char smraw[];
    __shared__ float sred[32][8];
    __shared__ float grow[32];
    const uint32_t smb = (smem_u32(smraw) + 255u) & ~255u;
    constexpr int OAH = 0, OAL = 4096, OBH = 8192, OBL = 8192 + 65536;

    const int z = blockIdx.y;
    const int bz = z >> 4;
    const int tid = threadIdx.x, lane = tid & 31, wid = tid >> 5;
    const int r0 = lane >> 2;

    const __half* Ah = qh_ + (long)z * S_ * DH_;
    const __half* Al = ql_ + (long)z * S_ * DH_;
    const __half* Bh = kh_ + (long)z * S_ * DH_;
    const __half* Bl = kl_ + (long)z * S_ * DH_;

    // stage ALL 512 k rows once (hi+lo) + first q tile
#pragma unroll
    for (int ii = 0; ii < 16; ii++) {
        int i = ii * 256 + tid;
        int r = i >> 3, ch = i & 7;
        cp16(smb + OBH + (uint32_t)swz128(r, ch << 3), Bh + (long)r * DH_ + ch * 8);
        cp16(smb + OBL + (uint32_t)swz128(r, ch << 3), Bl + (long)r * DH_ + ch * 8);
    }
    {
        const int m0f = blockIdx.x * 64;
        int r = tid >> 3, ch = tid & 7;
        cp16(smb + OAH + (uint32_t)swz128(r, ch << 3), Ah + (long)(m0f + r) * DH_ + ch * 8);
        cp16(smb + OAL + (uint32_t)swz128(r, ch << 3), Al + (long)(m0f + r) * DH_ + ch * 8);
    }
    cp_commit();

    for (int it = 0; it < 2; it++) {
        const int m0 = blockIdx.x * 64 + it * 32;
        cp_wait<0>();
        __syncthreads();

        float acc[2][8][4];
#pragma unroll
        for (int mt = 0; mt < 2; mt++)
#pragma unroll
            for (int nt = 0; nt < 8; nt++)
#pragma unroll
                for (int u = 0; u < 4; u++) acc[mt][nt][u] = 0.f;

#pragma unroll
        for (int k16 = 0; k16 < 4; k16++) {
            uint32_t aH[2][4], aL[2][4];
#pragma unroll
            for (int mt = 0; mt < 2; mt++) {
                int r  = mt * 16 + (lane & 15);
                int kk = k16 * 16 + ((lane >> 4) << 3);
                ldsm4(aH[mt], smb + OAH + swz128(r, kk));
                ldsm4(aL[mt], smb + OAL + swz128(r, kk));
            }
            uint32_t bH[8][2], bL[8][2];
#pragma unroll
            for (int nb2 = 0; nb2 < 4; nb2++) {
                int r  = wid * 64 + nb2 * 16 + ((lane >> 4) << 3) + (lane & 7);
                int kk = k16 * 16 + (((lane >> 3) & 1) << 3);
                uint32_t t4[4];
                ldsm4(t4, smb + OBH + swz128(r, kk));
                bH[2*nb2][0] = t4[0]; bH[2*nb2][1] = t4[1];
                bH[2*nb2+1][0] = t4[2]; bH[2*nb2+1][1] = t4[3];
                ldsm4(t4, smb + OBL + swz128(r, kk));
                bL[2*nb2][0] = t4[0]; bL[2*nb2][1] = t4[1];
                bL[2*nb2+1][0] = t4[2]; bL[2*nb2+1][1] = t4[3];
            }
#pragma unroll
            for (int mt = 0; mt < 2; mt++)
#pragma unroll
                for (int nt = 0; nt < 8; nt++) {
                    mma16816(acc[mt][nt], aH[mt], bH[nt]);
                    mma16816(acc[mt][nt], aH[mt], bL[nt]);
                    mma16816(acc[mt][nt], aL[mt], bH[nt]);
                }
        }
        __syncthreads();   // q reads done — safe to overwrite q buffer
        if (it == 0) {     // prefetch second q tile during softmax math
            const int m0n = blockIdx.x * 64 + 32;
            int r = tid >> 3, ch = tid & 7;
            cp16(smb + OAH + (uint32_t)swz128(r, ch << 3), Ah + (long)(m0n + r) * DH_ + ch * 8);
            cp16(smb + OAL + (uint32_t)swz128(r, ch << 3), Al + (long)(m0n + r) * DH_ + ch * 8);
        }
        cp_commit();

        // ---- band add + mask; rows owned: q = m0 + r0 + i*8, i = mt*2 + (u>>1) ----
        float mq[4];
#pragma unroll
        for (int i = 0; i < 4; i++)
            mq[i] = (float)mask[bz * S_ + m0 + r0 + i * 8];

        float rmax[4] = {-1e30f, -1e30f, -1e30f, -1e30f};
#pragma unroll
        for (int mt = 0; mt < 2; mt++)
#pragma unroll
            for (int nt = 0; nt < 8; nt++) {
                int nbase = wid * 64 + nt * 8 + (lane & 3) * 2;
#pragma unroll
                for (int u = 0; u < 4; u++) {
                    int i = mt * 2 + (u >> 1);
                    int q = m0 + r0 + i * 8;
                    int n = nbase + (u & 1);
                    float x = acc[mt][nt][u]
                        + c2pb[((long)z * S_ + q) * BW_ + (q & 127) + 512 - n]
                        + p2cb[((long)z * S_ + n) * BW_ + q - (n & 127) + 128];
                    float w = mq[i] * (float)mask[bz * S_ + n];
                    float s = (w > 0.f) ? x : -1e9f;
                    acc[mt][nt][u] = s;
                    rmax[i] = fmaxf(rmax[i], s);
                }
            }
#pragma unroll
        for (int i = 0; i < 4; i++) {
            rmax[i] = fmaxf(rmax[i], __shfl_xor_sync(0xffffffffu, rmax[i], 1));
            rmax[i] = fmaxf(rmax[i], __shfl_xor_sync(0xffffffffu, rmax[i], 2));
        }
        if ((lane & 3) == 0) {
#pragma unroll
            for (int i = 0; i < 4; i++) sred[r0 + i * 8][wid] = rmax[i];
        }
        __syncthreads();
        if (tid < 32) {
            float m = sred[tid][0];
#pragma unroll
            for (int w8 = 1; w8 < 8; w8++) m = fmaxf(m, sred[tid][w8]);
            grow[tid] = m;
        }
        __syncthreads();
        float gmax[4];
#pragma unroll
        for (int i = 0; i < 4; i++) gmax[i] = grow[r0 + i * 8];
        __syncthreads();

        // ---- exp + row sum ----
        float rsum[4] = {0.f, 0.f, 0.f, 0.f};
#pragma unroll
        for (int mt = 0; mt < 2; mt++)
#pragma unroll
            for (int nt = 0; nt < 8; nt++)
#pragma unroll
                for (int u = 0; u < 4; u++) {
                    int i = mt * 2 + (u >> 1);
                    float e = __expf(acc[mt][nt][u] - gmax[i]);
                    acc[mt][nt][u] = e;
                    rsum[i] += e;
                }
#pragma unroll
        for (int i = 0; i < 4; i++) {
            rsum[i] += __shfl_xor_sync(0xffffffffu, rsum[i], 1);
            rsum[i] += __shfl_xor_sync(0xffffffffu, rsum[i], 2);
        }
        if ((lane & 3) == 0) {
#pragma unroll
            for (int i = 0; i < 4; i++) sred[r0 + i * 8][wid] = rsum[i];
        }
        __syncthreads();
        if (tid < 32) {
            float s = 0.f;
#pragma unroll
            for (int w8 = 0; w8 < 8; w8++) s += sred[tid][w8];
            grow[tid] = 1.0f / s;
        }
        __syncthreads();
        float ginv[4];
#pragma unroll
        for (int i = 0; i < 4; i++) ginv[i] = grow[r0 + i * 8];

        // ---- write split-fp16 probs ----
#pragma unroll
        for (int mt = 0; mt < 2; mt++)
#pragma unroll
            for (int nt = 0; nt < 8; nt++) {
                int nbase = wid * 64 + nt * 8 + (lane & 3) * 2;
                float mk0 = (float)mask[bz * S_ + nbase];
                float mk1 = (float)mask[bz * S_ + nbase + 1];
                int i0 = mt * 2, i1 = mt * 2 + 1;
                int q0 = m0 + r0 + i0 * 8, q1 = q0 + 8;
                float p0 = acc[mt][nt][0] * ginv[i0] * (mq[i0] * mk0);
                float p1 = acc[mt][nt][1] * ginv[i0] * (mq[i0] * mk1);
                float p2 = acc[mt][nt][2] * ginv[i1] * (mq[i1] * mk0);
                float p3 = acc[mt][nt][3] * ginv[i1] * (mq[i1] * mk1);
                __half h0, l0, h1, l1;
                fsplit(p0, h0, l0); fsplit(p1, h1, l1);
                *(__half2*)(ph_ + ((long)z * S_ + q0) * S_ + nbase) = __halves2half2(h0, h1);
                *(__half2*)(pl_ + ((long)z * S_ + q0) * S_ + nbase) = __halves2half2(l0, l1);
                fsplit(p2, h0, l0); fsplit(p3, h1, l1);
                *(__half2*)(ph_ + ((long)z * S_ + q1) * S_ + nbase) = __halves2half2(h0, h1);
                *(__half2*)(pl_ + ((long)z * S_ + q1) * S_ + nbase) = __halves2half2(l0, l1);
            }
        __syncthreads();
    }
}

// ---------------- bulk fp32 -> split fp16 conversion ----------------
__global__ __launch_bounds__(256) void cvt_split_k(const float* __restrict__ x,
        __half* __restrict__ h, __half* __restrict__ l, int n4)
{
    int i = blockIdx.x * 256 + threadIdx.x;
    if (i >= n4) return;
    float4 v = *(const float4*)(x + 4 * (long)i);
    __half h0,l0,h1,l1,h2,l2,h3,l3;
    fsplit(v.x,h0,l0); fsplit(v.y,h1,l1); fsplit(v.z,h2,l2); fsplit(v.w,h3,l3);
    __half2 ha = __halves2half2(h0,h1), hb = __halves2half2(h2,h3);
    __half2 la = __halves2half2(l0,l1), lb = __halves2half2(l2,l3);
    uint2 hu, lu;
    hu.x = *(uint32_t*)&ha; hu.y = *(uint32_t*)&hb;
    lu.x = *(uint32_t*)&la; lu.y = *(uint32_t*)&lb;
    *(uint2*)(h + 4 * (long)i) = hu;
    *(uint2*)(l + 4 * (long)i) = lu;
}

// ---------------- split qkv -> split-fp16 q,k [b,h,s,d], vT [b,h,d,s] ----------------
__global__ void split_qkv_k(const float* __restrict__ qkv,
                            const float* __restrict__ qb,
                            const float* __restrict__ vb, float inv_scale)
{
    int idx = blockIdx.x * 256 + threadIdx.x;
    int d = idx & 63, h = (idx >> 6) & 15, s = (idx >> 10) & 511, b = idx >> 19;
    long base = (long)(b * S_ + s) * 3 * H_ + h * 3 * DH_;
    int o  = ((b * NH_ + h) * S_ + s) * DH_ + d;
    int ot = ((b * NH_ + h) * DH_ + d) * S_ + s;
    __half hh, ll;
    fsplit((qkv[base + d] + qb[h * DH_ + d]) * inv_scale, hh, ll);
    g_qh[o] = hh; g_ql[o] = ll;
    fsplit(qkv[base + DH_ + d], hh, ll);
    g_kh[o] = hh; g_kl[o] = ll;
    fsplit(qkv[base + 2 * DH_ + d] + vb[h * DH_ + d], hh, ll);
    g_vTh[ot] = hh; g_vTl[ot] = ll;
}

// ---------------- h = LN(h + delta), emits fp32 h and split fp16 ----------------
__global__ __launch_bounds__(256) void add_ln_k(float* __restrict__ hb,
        const float* __restrict__ dl, const float* __restrict__ sc,
        const float* __restrict__ bc, float eps)
{
    long t = blockIdx.x;
    float* x = hb + t * H_;
    const float* d = dl + t * H_;
    int tid = threadIdx.x;
    float v[4]; float ls = 0.f;
#pragma unroll
    for (int j = 0; j < 4; j++) { int i = tid + (j << 8); v[j] = x[i] + d[i]; ls += v[j]; }
    float mu = blk_sum256(ls) * (1.0f / H_);
    float lv = 0.f;
#pragma unroll
    for (int j = 0; j < 4; j++) { float dd = v[j] - mu; lv += dd * dd; }
    float var = blk_sum256(lv) * (1.0f / H_);
    float rstd = rsqrtf(var + eps);
#pragma unroll
    for (int j = 0; j < 4; j++) {
        int i = tid + (j << 8);
        float y = (v[j] - mu) * rstd * sc[i] + bc[i];
        x[i] = y;
        __half hh, ll; fsplit(y, hh, ll);
        g_hh[t * H_ + i] = hh; g_hl[t * H_ + i] = ll;
    }
}

// ---------------- embedding gather + LN * mask ----------------
__global__ __launch_bounds__(256) void embed_k(const int* __restrict__ ids,
        const int* __restrict__ mask, const float* __restrict__ we,
        const float* __restrict__ s, const float* __restrict__ bb)
{
    int t = blockIdx.x;
    long ro = (long)ids[t] * H_;
    float mf = (float)mask[t];
    int tid = threadIdx.x;
    float v[4]; float ls = 0.f;
#pragma unroll
    for (int j = 0; j < 4; j++) { v[j] = we[ro + tid + (j << 8)]; ls += v[j]; }
    float mu = blk_sum256(ls) * (1.0f / H_);
    float lv = 0.f;
#pragma unroll
    for (int j = 0; j < 4; j++) { float dd = v[j] - mu; lv += dd * dd; }
    float var = blk_sum256(lv) * (1.0f / H_);
    float rstd = rsqrtf(var + 1e-7f);
#pragma unroll
    for (int j = 0; j < 4; j++) {
        int i = tid + (j << 8);
        float y = ((v[j] - mu) * rstd * s[i] + bb[i]) * mf;
        g_h[(long)t * H_ + i] = y;
        __half hh, ll; fsplit(y, hh, ll);
        g_hh[(long)t * H_ + i] = hh; g_hl[(long)t * H_ + i] = ll;
    }
}

// ---------------- head ----------------
__global__ __launch_bounds__(256) void head_k(const float* __restrict__ hb,
        const float* __restrict__ s, const float* __restrict__ bb,
        const float* __restrict__ ow, const float* __restrict__ ob,
        float* __restrict__ out)
{
    int b = blockIdx.x;
    const float* x = hb + (long)b * S_ * H_;
    int tid = threadIdx.x;
    float v[4]; float ls = 0.f;
#pragma unroll
    for (int j = 0; j < 4; j++) { v[j] = x[tid + (j << 8)]; ls += v[j]; }
    float mu = blk_sum256(ls) * (1.0f / H_);
    float lv = 0.f;
#pragma unroll
    for (int j = 0; j < 4; j++) { float dd = v[j] - mu; lv += dd * dd; }
    float var = blk_sum256(lv) * (1.0f / H_);
    float rstd = rsqrtf(var + 1e-5f);
    float ld = 0.f;
#pragma unroll
    for (int j = 0; j < 4; j++) {
        int i = tid + (j << 8);
        float y = (v[j] - mu) * rstd * s[i] + bb[i];
        ld += y * ow[i];
    }
    float dot = blk_sum256(ld);
    if (tid == 0) out[b] = dot + ob[0];
}

// ---------------- host orchestration ----------------
#define SM_128_128 98560
#define SM_128_64  73984
#define SM_64_64   49408

extern "C" void kernel_launch(void* const* d_in, const int* in_sizes, int n_in,
                              void* d_out, int out_size)
{
    const int*   ids       = (const int*)  d_in[0];
    const int*   mask      = (const int*)  d_in[1];
    const float* word_emb  = (const float*)d_in[3];
    const float* emb_ln_s  = (const float*)d_in[4];
    const float* emb_ln_b  = (const float*)d_in[5];
    const float* rel_emb   = (const float*)d_in[6];
    const float* in_w      = (const float*)d_in[7];
    const float* q_bias    = (const float*)d_in[8];
    const float* v_bias    = (const float*)d_in[9];
    const float* pos_k_w   = (const float*)d_in[10];
    const float* pos_q_w   = (const float*)d_in[11];
    const float* pos_q_b   = (const float*)d_in[12];
    const float* attn_o_w  = (const float*)d_in[13];
    const float* attn_o_b  = (const float*)d_in[14];
    const float* ln1_s     = (const float*)d_in[15];
    const float* ln1_b     = (const float*)d_in[16];
    const float* ffn_w1    = (const float*)d_in[17];
    const float* ffn_b1    = (const float*)d_in[18];
    const float* ffn_w2    = (const float*)d_in[19];
    const float* ffn_b2    = (const float*)d_in[20];
    const float* ln2_s     = (const float*)d_in[21];
    const float* ln2_b     = (const float*)d_in[22];
    const float* head_ln_s = (const float*)d_in[23];
    const float* head_ln_b = (const float*)d_in[24];
    const float* out_w     = (const float*)d_in[25];
    const float* out_b     = (const float*)d_in[26];
    float* out = (float*)d_out;

    float *h_, *qkv_, *band_, *t2_;
    cudaGetSymbolAddress((void**)&h_,   g_h);
    cudaGetSymbolAddress((void**)&qkv_, g_qkv);
    cudaGetSymbolAddress((void**)&band_,g_band);
    cudaGetSymbolAddress((void**)&t2_,  g_t2);
    float* c2p_ = band_;
    float* p2c_ = band_ + (size_t)ZBH_ * S_ * BW_;

    __half *wih,*wil,*ppwh,*ppwl,*aowh,*aowl,*w1h,*w1l,*w2h,*w2l,*relh,*rell;
    cudaGetSymbolAddress((void**)&wih,  g_wih);  cudaGetSymbolAddress((void**)&wil,  g_wil);
    cudaGetSymbolAddress((void**)&ppwh, g_ppwh); cudaGetSymbolAddress((void**)&ppwl, g_ppwl);
    cudaGetSymbolAddress((void**)&aowh, g_aowh); cudaGetSymbolAddress((void**)&aowl, g_aowl);
    cudaGetSymbolAddress((void**)&w1h,  g_w1h);  cudaGetSymbolAddress((void**)&w1l,  g_w1l);
    cudaGetSymbolAddress((void**)&w2h,  g_w2h);  cudaGetSymbolAddress((void**)&w2l,  g_w2l);
    cudaGetSymbolAddress((void**)&relh, g_relh); cudaGetSymbolAddress((void**)&rell, g_rell);

    __half *hh,*hl,*qh,*ql,*kh,*kl,*vTh,*vTl,*ppoh,*ppol,*ph,*pl,*cxh,*cxl,*ffh,*ffl;
    cudaGetSymbolAddress((void**)&hh,  g_hh);  cudaGetSymbolAddress((void**)&hl,  g_hl);
    cudaGetSymbolAddress((void**)&qh,  g_qh);  cudaGetSymbolAddress((void**)&ql,  g_ql);
    cudaGetSymbolAddress((void**)&kh,  g_kh);  cudaGetSymbolAddress((void**)&kl,  g_kl);
    cudaGetSymbolAddress((void**)&vTh, g_vTh); cudaGetSymbolAddress((void**)&vTl, g_vTl);
    cudaGetSymbolAddress((void**)&ppoh,g_ppoh);cudaGetSymbolAddress((void**)&ppol,g_ppol);
    cudaGetSymbolAddress((void**)&ph,  g_ph);  cudaGetSymbolAddress((void**)&pl,  g_pl);
    cudaGetSymbolAddress((void**)&cxh, g_cxh); cudaGetSymbolAddress((void**)&cxl, g_cxl);
    cudaGetSymbolAddress((void**)&ffh, g_ffh); cudaGetSymbolAddress((void**)&ffl, g_ffl);

    cudaFuncSetAttribute(hgemm<128,64 ,false,false,0,0,false>, cudaFuncAttributeMaxDynamicSharedMemorySize, SM_128_64);
    cudaFuncSetAttribute(hgemm<128,64 ,true ,true ,1,0,false>, cudaFuncAttributeMaxDynamicSharedMemorySize, SM_128_64);
    cudaFuncSetAttribute(hgemm<128,128,false,false,0,3,false>, cudaFuncAttributeMaxDynamicSharedMemorySize, SM_128_128);
    cudaFuncSetAttribute(hgemm<64 ,64 ,false,true ,1,0,true >, cudaFuncAttributeMaxDynamicSharedMemorySize, SM_64_64);
    cudaFuncSetAttribute(hgemm<64 ,64 ,false,false,1,0,false>, cudaFuncAttributeMaxDynamicSharedMemorySize, SM_64_64);
    cudaFuncSetAttribute(hgemm<64 ,64 ,false,true ,0,0,false>, cudaFuncAttributeMaxDynamicSharedMemorySize, SM_64_64);
    cudaFuncSetAttribute(fused_sm_k, cudaFuncAttributeMaxDynamicSharedMemorySize, SM_FA);

    const float inv_scale = 1.0f / sqrtf(3.0f * DH_);

    // ---- weight conversion ----
    cvt_split_k<<<(NIW/4 + 255)/256, 256>>>(in_w,     wih,  wil,  NIW/4);
    cvt_split_k<<<(NPW/4 + 255)/256, 256>>>(pos_k_w,  ppwh,       ppwl,       NPW/4);
    cvt_split_k<<<(NPW/4 + 255)/256, 256>>>(pos_q_w,  ppwh + NPW, ppwl + NPW, NPW/4);
    cvt_split_k<<<(NPW/4 + 255)/256, 256>>>(attn_o_w, aowh, aowl, NPW/4);
    cvt_split_k<<<(NW1/4 + 255)/256, 256>>>(ffn_w1,   w1h,  w1l,  NW1/4);
    cvt_split_k<<<(NW1/4 + 255)/256, 256>>>(ffn_w2,   w2h,  w2l,  NW1/4);
    cvt_split_k<<<(R2_*H_/4 + 255)/256, 256>>>(rel_emb, relh, rell, R2_*H_/4);

    embed_k<<<BS_, 256>>>(ids, mask, word_emb, emb_ln_s, emb_ln_b);

    // ---- ALL layers' pk (z<12) / pq (z>=12) in one batched launch ----
    hgemm<64,64,false,true,1,0,true><<<dim3(16, 16, 2*L_), 256, SM_64_64>>>(
        relh, rell, H_, 0, ppwh, ppwl, H_, (long)H_*H_, 0,
        nullptr, ppoh, ppol, H_, 0, (long)R2_*H_, 0,
        pos_q_b, inv_scale, H_, nullptr, nullptr);

    for (int l = 0; l < L_; l++) {
        // qkv = h @ in_w^T -> fp32
        hgemm<128,64,false,false,0,0,false><<<dim3(48, 8, 1), 256, SM_128_64>>>(
            hh, hl, H_, 0, wih + (long)l*3*H_*H_, wil + (long)l*3*H_*H_, H_, 0, 0,
            qkv_, nullptr, nullptr, 3*H_, 0, 0, 0, nullptr, 1.f, H_,
            nullptr, nullptr);
        split_qkv_k<<<(B_*S_*H_)/256, 256>>>(qkv_, q_bias + l*H_, v_bias + l*H_, inv_scale);

        // DUAL banded: z<32 c2p = q @ pk_l^T; z>=32 p2c = k @ pq_l^T
        hgemm<128,128,false,false,0,3,false><<<dim3(5, 4, 2*ZBH_), 256, SM_128_128>>>(
            qh, ql, DH_, (long)S_*DH_,
            ppoh + (long)l*R2_*H_, ppol + (long)l*R2_*H_, H_, DH_, NH_,
            band_, nullptr, nullptr, BW_, 0, (long)S_*BW_, 0,
            nullptr, 1.f, DH_, kh, kl);

        // fused scores + band gathers + masked softmax -> split-fp16 probs
        fused_sm_k<<<dim3(8, 32), 256, SM_FA>>>(
            qh, ql, kh, kl, c2p_, p2c_, ph, pl, mask);

        // ctx = probs @ v -> split fp16
        hgemm<64,64,false,false,1,0,false><<<dim3(1, 8, B_*NH_), 256, SM_64_64>>>(
            ph, pl, S_, (long)S_*S_, vTh, vTl, S_, (long)DH_*S_, 0,
            nullptr, cxh, cxl, H_, (long)S_*H_, DH_, NH_, nullptr, 1.f, S_,
            nullptr, nullptr);

        // attn out proj -> fp32 t2; residual LN
        hgemm<64,64,false,true,0,0,false><<<dim3(16, 16, 1), 256, SM_64_64>>>(
            cxh, cxl, H_, 0, aowh + (long)l*H_*H_, aowl + (long)l*H_*H_, H_, 0, 0,
            t2_, nullptr, nullptr, H_, 0, 0, 0, attn_o_b + l*H_, 1.f, H_,
            nullptr, nullptr);
        add_ln_k<<<BS_, 256>>>(h_, t2_, ln1_s + l*H_, ln1_b + l*H_, LN_EPS_);

        // FFN
        hgemm<128,64,true,true,1,0,false><<<dim3(64, 8, 1), 256, SM_128_64>>>(
            hh, hl, H_, 0, w1h + (long)l*FF_*H_, w1l + (long)l*FF_*H_, H_, 0, 0,
            nullptr, ffh, ffl, FF_, 0, 0, 0, ffn_b1 + l*FF_, 1.f, H_,
            nullptr, nullptr);
        hgemm<64,64,false,true,0,0,false><<<dim3(16, 16, 1), 256, SM_64_64>>>(
            ffh, ffl, FF_, 0, w2h + (long)l*H_*FF_, w2l + (long)l*H_*FF_, FF_, 0, 0,
            t2_, nullptr, nullptr, H_, 0, 0, 0, ffn_b2 + l*H_, 1.f, FF_,
            nullptr, nullptr);
        add_ln_k<<<BS_, 256>>>(h_, t2_, ln2_s + l*H_, ln2_b + l*H_, LN_EPS_);
    }

    head_k<<<B_, 256>>>(h_, head_ln_s, head_ln_b, out_w, out_b, out);
}